// round 1
// baseline (speedup 1.0000x reference)
#include <cuda_runtime.h>
#include <cstddef>

#define NPTS 500000
#define DIM  128
#define KC   1024

// ---------------- scratch (no allocations allowed) ----------------
__device__ float g_sums[KC * DIM];
__device__ float g_counts[KC];
__device__ float g_c2[KC];

// ---------------- kernel 1: zero scratch ----------------
__global__ void zero_kernel() {
    int i = blockIdx.x * blockDim.x + threadIdx.x;
    if (i < KC * DIM) g_sums[i] = 0.0f;
    if (i < KC)       g_counts[i] = 0.0f;
}

// ---------------- kernel 2: segment sum (warp per point) ----------------
__global__ void segsum_kernel(const float* __restrict__ vecs,
                              const int*   __restrict__ asg) {
    int gw   = (blockIdx.x * blockDim.x + threadIdx.x) >> 5;
    int lane = threadIdx.x & 31;
    if (gw >= NPTS) return;
    int k = asg[gw];
    float4 v = *((const float4*)(vecs + (size_t)gw * DIM) + lane);
    atomicAdd(((float4*)(g_sums + (size_t)k * DIM)) + lane, v);
    if (lane == 0) atomicAdd(&g_counts[k], 1.0f);
}

// ---------------- kernel 3: centroids = sums/counts, c2 ----------------
__global__ void finalize_kernel(float* __restrict__ out_cent) {
    int k = blockIdx.x;
    int d = threadIdx.x;
    float c = g_sums[k * DIM + d] / g_counts[k];
    out_cent[k * DIM + d] = c;

    float s = c * c;
    #pragma unroll
    for (int o = 16; o > 0; o >>= 1) s += __shfl_down_sync(0xffffffffu, s, o);
    __shared__ float ws[4];
    if ((d & 31) == 0) ws[d >> 5] = s;
    __syncthreads();
    if (d == 0) g_c2[k] = (ws[0] + ws[1]) + (ws[2] + ws[3]);
}

// ---------------- kernel 4: distance argmin ----------------
// Block: 128 points x all 1024 clusters (8 chunks of 128).
// Thread tile: 4 points x 16 clusters. 256 threads.
//   m = tid&31  -> points 4m..4m+3  (float4 smem read, XOR-swizzled, conflict-free)
//   g = tid>>5  -> clusters 16g..16g+15 (warp-uniform -> broadcast smem reads)
#define TP   128
#define TCC  128
#define NCHUNK (KC / TCC)
#define ATHREADS 256

// smem: pts[128][128] swizzled + cent[128][128] row-major + c2s[128] + x2s[128]
#define SMEM_FLOATS (DIM*TP + TCC*DIM + TCC + TP)
#define SMEM_BYTES  (SMEM_FLOATS * (int)sizeof(float))

__global__ __launch_bounds__(ATHREADS, 1)
void argmin_kernel(const float* __restrict__ vecs,
                   const float* __restrict__ cent,
                   float* __restrict__ out_asg) {
    extern __shared__ float sm[];
    float* pts = sm;                  // (d,p) -> d*TP + (p ^ (4*((d>>2)&7)))
    float* cs  = sm + DIM * TP;       // [c][d] row-major (chunk)
    float* c2s = cs + TCC * DIM;      // [TCC]
    float* x2s = c2s + TCC;           // [TP]

    const int tid  = threadIdx.x;
    const int lane = tid & 31;
    const int warp = tid >> 5;
    const int base = blockIdx.x * TP;

    // ---- stage points (transposed + swizzled), compute x2 on the fly ----
    for (int r = 0; r < TP / 8; r++) {
        int p = warp * (TP / 8) + r;
        int n = base + p;
        if (n >= NPTS) n = NPTS - 1;               // clamp (dup work, guarded store)
        float4 v = *((const float4*)(vecs + (size_t)n * DIM) + lane);
        int q = p ^ (4 * (lane & 7));              // d>>2 == lane for d=4*lane+j
        pts[(4 * lane + 0) * TP + q] = v.x;
        pts[(4 * lane + 1) * TP + q] = v.y;
        pts[(4 * lane + 2) * TP + q] = v.z;
        pts[(4 * lane + 3) * TP + q] = v.w;
        float s = v.x * v.x + v.y * v.y + v.z * v.z + v.w * v.w;
        #pragma unroll
        for (int o = 16; o > 0; o >>= 1) s += __shfl_down_sync(0xffffffffu, s, o);
        if (lane == 0) x2s[p] = s;
    }
    __syncthreads();

    const int m = tid & 31;
    const int g = tid >> 5;

    float x2r[4];
    #pragma unroll
    for (int i = 0; i < 4; i++) x2r[i] = x2s[4 * m + i];

    float bestv[4];
    int   besti[4];
    #pragma unroll
    for (int i = 0; i < 4; i++) { bestv[i] = 3.402823466e38f; besti[i] = 0; }

    for (int chunk = 0; chunk < NCHUNK; chunk++) {
        // stage centroid chunk (row-major copy, coalesced)
        {
            const float4* src = (const float4*)(cent + (size_t)chunk * TCC * DIM);
            float4* dst = (float4*)cs;
            #pragma unroll
            for (int i = 0; i < (TCC * DIM / 4) / ATHREADS; i++)
                dst[tid + i * ATHREADS] = src[tid + i * ATHREADS];
            if (tid < TCC) c2s[tid] = g_c2[chunk * TCC + tid];
        }
        __syncthreads();

        float acc[4][16];
        #pragma unroll
        for (int i = 0; i < 4; i++)
            #pragma unroll
            for (int j = 0; j < 16; j++) acc[i][j] = 0.0f;

        const float* crow = cs + (size_t)(16 * g) * DIM;  // warp-uniform
        #pragma unroll 4
        for (int d = 0; d < DIM; d++) {
            float4 a = *((const float4*)(pts + d * TP + 4 * (m ^ ((d >> 2) & 7))));
            #pragma unroll
            for (int j = 0; j < 16; j++) {
                float b = crow[j * DIM + d];               // broadcast
                acc[0][j] = fmaf(a.x, b, acc[0][j]);
                acc[1][j] = fmaf(a.y, b, acc[1][j]);
                acc[2][j] = fmaf(a.z, b, acc[2][j]);
                acc[3][j] = fmaf(a.w, b, acc[3][j]);
            }
        }

        // fold into running min (ascending cluster index, strict < keeps first)
        #pragma unroll
        for (int j = 0; j < 16; j++) {
            int   cidx = chunk * TCC + 16 * g + j;
            float c2v  = c2s[16 * g + j];
            #pragma unroll
            for (int i = 0; i < 4; i++) {
                float t    = c2v + x2r[i];
                float dist = t - 2.0f * acc[i][j];
                if (dist < bestv[i]) { bestv[i] = dist; besti[i] = cidx; }
            }
        }
        __syncthreads();   // protect cs before next chunk load / reuse
    }

    // ---- cross-g reduction via smem (reuse cs) ----
    float* rval = cs;                      // [8][TP]
    int*   ridx = (int*)(cs + 8 * TP);     // [8][TP]
    #pragma unroll
    for (int i = 0; i < 4; i++) {
        rval[g * TP + 4 * m + i] = bestv[i];
        ridx[g * TP + 4 * m + i] = besti[i];
    }
    __syncthreads();

    if (tid < TP) {
        float bv = rval[tid];
        int   bi = ridx[tid];
        #pragma unroll
        for (int g2 = 1; g2 < 8; g2++) {
            float v  = rval[g2 * TP + tid];
            int   ix = ridx[g2 * TP + tid];
            if (v < bv || (v == bv && ix < bi)) { bv = v; bi = ix; }
        }
        int n = base + tid;
        if (n < NPTS) out_asg[n] = (float)bi;
    }
}

// ---------------- launch ----------------
extern "C" void kernel_launch(void* const* d_in, const int* in_sizes, int n_in,
                              void* d_out, int out_size) {
    const float* vecs = (const float*)d_in[0];
    const int*   asg  = (const int*)d_in[1];
    float* out      = (float*)d_out;
    float* out_cent = out;             // [KC*DIM]
    float* out_asg  = out + KC * DIM;  // [NPTS]

    zero_kernel<<<(KC * DIM + 255) / 256, 256>>>();
    segsum_kernel<<<(NPTS * 32) / 256, 256>>>(vecs, asg);
    finalize_kernel<<<KC, DIM>>>(out_cent);

    cudaFuncSetAttribute(argmin_kernel,
                         cudaFuncAttributeMaxDynamicSharedMemorySize, SMEM_BYTES);
    int ablocks = (NPTS + TP - 1) / TP;
    argmin_kernel<<<ablocks, ATHREADS, SMEM_BYTES>>>(vecs, out_cent, out_asg);
}

// round 4
// speedup vs baseline: 1.7438x; 1.7438x over previous
#include <cuda_runtime.h>
#include <cuda_bf16.h>
#include <cstdint>
#include <cstddef>

#define NPTS 500000
#define DIM  128
#define KC   1024

// ---------------- scratch ----------------
__device__ float g_sums[KC * DIM];
__device__ float g_counts[KC];
__device__ float g_c2[KC];
__device__ __nv_bfloat16 g_cent_hi[KC * DIM];   // splits of -2*centroid
__device__ __nv_bfloat16 g_cent_mi[KC * DIM];
__device__ __nv_bfloat16 g_cent_lo[KC * DIM];

// ---------------- helpers ----------------
__device__ __forceinline__ uint32_t smem_u32(const void* p) {
    uint32_t a;
    asm("{ .reg .u64 t; cvta.to.shared.u64 t, %1; cvt.u32.u64 %0, t; }" : "=r"(a) : "l"(p));
    return a;
}
__device__ __forceinline__ void ldsm_x4(uint32_t* r, uint32_t addr) {
    asm volatile("ldmatrix.sync.aligned.m8n8.x4.shared.b16 {%0,%1,%2,%3}, [%4];"
        : "=r"(r[0]), "=r"(r[1]), "=r"(r[2]), "=r"(r[3]) : "r"(addr));
}
__device__ __forceinline__ void mma_bf16(float* d, const uint32_t* a, uint32_t b0, uint32_t b1) {
    asm volatile("mma.sync.aligned.m16n8k16.row.col.f32.bf16.bf16.f32 "
        "{%0,%1,%2,%3}, {%4,%5,%6,%7}, {%8,%9}, {%0,%1,%2,%3};"
        : "+f"(d[0]), "+f"(d[1]), "+f"(d[2]), "+f"(d[3])
        : "r"(a[0]), "r"(a[1]), "r"(a[2]), "r"(a[3]), "r"(b0), "r"(b1));
}
__device__ __forceinline__ void cp16(uint32_t dst, const void* src) {
    asm volatile("cp.async.cg.shared.global [%0], [%1], 16;" :: "r"(dst), "l"(src) : "memory");
}
#define CP_COMMIT() asm volatile("cp.async.commit_group;" ::: "memory")
#define CP_WAIT0()  asm volatile("cp.async.wait_group 0;" ::: "memory")
#define CP_WAIT1()  asm volatile("cp.async.wait_group 1;" ::: "memory")

// ---------------- kernel 1: zero scratch ----------------
__global__ void zero_kernel() {
    int i = blockIdx.x * blockDim.x + threadIdx.x;
    if (i < KC * DIM) g_sums[i] = 0.0f;
    if (i < KC)       g_counts[i] = 0.0f;
}

// ---------------- kernel 2: segment sum ----------------
__global__ void segsum_kernel(const float* __restrict__ vecs,
                              const int*   __restrict__ asg) {
    int gw   = (blockIdx.x * blockDim.x + threadIdx.x) >> 5;
    int lane = threadIdx.x & 31;
    if (gw >= NPTS) return;
    int k = asg[gw];
    float4 v = *((const float4*)(vecs + (size_t)gw * DIM) + lane);
    atomicAdd(((float4*)(g_sums + (size_t)k * DIM)) + lane, v);
    if (lane == 0) atomicAdd(&g_counts[k], 1.0f);
}

// ---------------- kernel 3: centroids, c2, -2c bf16 splits ----------------
__global__ void finalize_kernel(float* __restrict__ out_cent) {
    int k = blockIdx.x;
    int d = threadIdx.x;
    float c = g_sums[k * DIM + d] / g_counts[k];
    out_cent[k * DIM + d] = c;

    float m = -2.0f * c;
    __nv_bfloat16 h = __float2bfloat16(m);
    float r1 = m - __bfloat162float(h);
    __nv_bfloat16 mi = __float2bfloat16(r1);
    float r2 = r1 - __bfloat162float(mi);
    __nv_bfloat16 lo = __float2bfloat16(r2);
    g_cent_hi[k * DIM + d] = h;
    g_cent_mi[k * DIM + d] = mi;
    g_cent_lo[k * DIM + d] = lo;

    float s = c * c;
    #pragma unroll
    for (int o = 16; o > 0; o >>= 1) s += __shfl_down_sync(0xffffffffu, s, o);
    __shared__ float ws[4];
    if ((d & 31) == 0) ws[d >> 5] = s;
    __syncthreads();
    if (d == 0) g_c2[k] = (ws[0] + ws[1]) + (ws[2] + ws[3]);
}

// ---------------- kernel 4: mma.sync GEMM + argmin ----------------
// 128 points/CTA x 1024 clusters. 8 warps; warp w owns points 16w..16w+15.
// A: 3 bf16 splits of points, swizzled smem [3][128][256B].
// B: 3 bf16 splits of -2c, 64-cluster chunks, cp.async double-buffered.
// 6 product passes (hh,hm,mh,mm,hl,lh) accumulate into one fp32 D.
#define CH_N   16
#define CHW    64
#define A_SPLIT 32768
#define A_OFF   0
#define B_OFF   98304
#define B_BUF   49152
#define B_SPLIT 16384
#define C2_OFF  196608
#define X2P_OFF 200704
#define X2_OFF  201728
#define SM_TOTAL 202304

__global__ __launch_bounds__(256, 1)
void argmin_mma_kernel(const float* __restrict__ vecs, float* __restrict__ out_asg) {
    extern __shared__ __align__(1024) char sm[];
    const uint32_t su = smem_u32(sm);
    float* c2s = (float*)(sm + C2_OFF);
    float* x2p = (float*)(sm + X2P_OFF);
    float* x2s = (float*)(sm + X2_OFF);
    const int tid  = threadIdx.x;
    const int lane = tid & 31;
    const int w    = tid >> 5;
    const int base = blockIdx.x * 128;

    for (int i = tid; i < KC; i += 256) c2s[i] = g_c2[i];

    // ---- A convert: fp32 -> 3x bf16 splits into swizzled smem; x2 partials ----
    {
        int p = tid >> 1, h = tid & 1;
        int n = base + p; if (n >= NPTS) n = NPTS - 1;
        const float4* src = (const float4*)(vecs + (size_t)n * DIM) + h * 16;
        float s2 = 0.0f;
        const uint32_t rowb = (uint32_t)p * 256u;
        const uint32_t psw  = (uint32_t)(p & 7);
        #pragma unroll
        for (int j = 0; j < 16; j++) {
            float4 v = src[j];
            int d0 = h * 64 + j * 4;
            #pragma unroll
            for (int q = 0; q < 2; q++) {
                float a0 = q ? v.z : v.x;
                float a1 = q ? v.w : v.y;
                int   d  = d0 + 2 * q;
                s2 = fmaf(a0, a0, s2); s2 = fmaf(a1, a1, s2);
                __nv_bfloat16 h0 = __float2bfloat16(a0);
                float r0 = a0 - __bfloat162float(h0);
                __nv_bfloat16 m0 = __float2bfloat16(r0);
                __nv_bfloat16 l0 = __float2bfloat16(r0 - __bfloat162float(m0));
                __nv_bfloat16 h1 = __float2bfloat16(a1);
                float r1 = a1 - __bfloat162float(h1);
                __nv_bfloat16 m1 = __float2bfloat16(r1);
                __nv_bfloat16 l1 = __float2bfloat16(r1 - __bfloat162float(m1));
                uint32_t off = rowb + ((((uint32_t)(d >> 3)) ^ psw) << 4) + (uint32_t)(d & 7) * 2u;
                __nv_bfloat162 ph(h0, h1), pm(m0, m1), pl(l0, l1);
                *(uint32_t*)(sm + A_OFF + 0 * A_SPLIT + off) = *(uint32_t*)&ph;
                *(uint32_t*)(sm + A_OFF + 1 * A_SPLIT + off) = *(uint32_t*)&pm;
                *(uint32_t*)(sm + A_OFF + 2 * A_SPLIT + off) = *(uint32_t*)&pl;
            }
        }
        x2p[tid] = s2;
    }

    // ---- issue chunk 0 B loads ----
    #pragma unroll
    for (int s = 0; s < 3; s++) {
        const __nv_bfloat16* g = (s == 0) ? g_cent_hi : (s == 1) ? g_cent_mi : g_cent_lo;
        const char* gb = (const char*)g;   // chunk 0
        #pragma unroll
        for (int it = 0; it < 4; it++) {
            int idx = tid + it * 256;
            int row = idx >> 4, kg = idx & 15;
            uint32_t dst = su + B_OFF + (uint32_t)s * B_SPLIT + (uint32_t)row * 256u
                         + ((uint32_t)(kg ^ (row & 7)) << 4);
            cp16(dst, gb + (size_t)idx * 16);
        }
    }
    CP_COMMIT();
    __syncthreads();
    if (tid < 128) x2s[tid] = x2p[2 * tid] + x2p[2 * tid + 1];

    const int p0 = w * 16;
    float best[2] = {3.402823466e38f, 3.402823466e38f};
    int   bi[2]   = {0, 0};

    const int arow = p0 + (lane & 15);
    const uint32_t abase = su + A_OFF + (uint32_t)arow * 256u;
    const uint32_t arsw  = (uint32_t)(arow & 7);
    const int akg  = lane >> 4;
    const int brow_local = ((lane >> 4) << 3) + (lane & 7);
    const int bkg_half   = (lane >> 3) & 1;

    for (int ch = 0; ch < CH_N; ch++) {
        const int buf = ch & 1;
        if (ch + 1 < CH_N) {
            #pragma unroll
            for (int s = 0; s < 3; s++) {
                const __nv_bfloat16* g = (s == 0) ? g_cent_hi : (s == 1) ? g_cent_mi : g_cent_lo;
                const char* gb = (const char*)(g + (size_t)(ch + 1) * CHW * DIM);
                #pragma unroll
                for (int it = 0; it < 4; it++) {
                    int idx = tid + it * 256;
                    int row = idx >> 4, kg = idx & 15;
                    uint32_t dst = su + B_OFF + (uint32_t)(buf ^ 1) * B_BUF
                                 + (uint32_t)s * B_SPLIT + (uint32_t)row * 256u
                                 + ((uint32_t)(kg ^ (row & 7)) << 4);
                    cp16(dst, gb + (size_t)idx * 16);
                }
            }
            CP_COMMIT();
            CP_WAIT1();
        } else {
            CP_WAIT0();
        }
        __syncthreads();

        float D[8][4];
        #pragma unroll
        for (int i = 0; i < 8; i++)
            #pragma unroll
            for (int j = 0; j < 4; j++) D[i][j] = 0.0f;

        const uint32_t bbase = su + B_OFF + (uint32_t)buf * B_BUF;

        #pragma unroll
        for (int ks = 0; ks < 8; ks++) {
            uint32_t A_[3][4];
            {
                uint32_t ag = (uint32_t)(ks * 2 + akg);
                uint32_t asw = ((ag ^ arsw) << 4);
                ldsm_x4(A_[0], abase + 0 * A_SPLIT + asw);
                ldsm_x4(A_[1], abase + 1 * A_SPLIT + asw);
                ldsm_x4(A_[2], abase + 2 * A_SPLIT + asw);
            }
            uint32_t B_[3][4][4];
            #pragma unroll
            for (int pp = 0; pp < 4; pp++) {
                int r  = pp * 16 + brow_local;
                int kg = ks * 2 + bkg_half;
                uint32_t bad = bbase + (uint32_t)r * 256u + ((uint32_t)(kg ^ (r & 7)) << 4);
                ldsm_x4(B_[0][pp], bad + 0 * B_SPLIT);
                ldsm_x4(B_[1][pp], bad + 1 * B_SPLIT);
                ldsm_x4(B_[2][pp], bad + 2 * B_SPLIT);
            }
            // passes: (sa,sb) = hh, hm, mh, mm, hl, lh
            const int SA[6] = {0, 0, 1, 1, 0, 2};
            const int SB[6] = {0, 1, 0, 1, 2, 0};
            #pragma unroll
            for (int p6 = 0; p6 < 6; p6++) {
                #pragma unroll
                for (int pp = 0; pp < 4; pp++) {
                    mma_bf16(D[pp * 2 + 0], A_[SA[p6]], B_[SB[p6]][pp][0], B_[SB[p6]][pp][1]);
                    mma_bf16(D[pp * 2 + 1], A_[SA[p6]], B_[SB[p6]][pp][2], B_[SB[p6]][pp][3]);
                }
            }
        }

        // ---- fold argmin (ascending cluster order within lane) ----
        float x2a = x2s[p0 + (lane >> 2)];
        float x2b = x2s[p0 + (lane >> 2) + 8];
        #pragma unroll
        for (int nt = 0; nt < 8; nt++) {
            int cb = ch * 64 + nt * 8 + 2 * (lane & 3);
            float c20 = c2s[cb], c21 = c2s[cb + 1];
            float v;
            v = (c20 + x2a) + D[nt][0]; if (v < best[0]) { best[0] = v; bi[0] = cb; }
            v = (c21 + x2a) + D[nt][1]; if (v < best[0]) { best[0] = v; bi[0] = cb + 1; }
            v = (c20 + x2b) + D[nt][2]; if (v < best[1]) { best[1] = v; bi[1] = cb; }
            v = (c21 + x2b) + D[nt][3]; if (v < best[1]) { best[1] = v; bi[1] = cb + 1; }
        }
        __syncthreads();
    }

    // ---- reduce across the 4 lanes sharing each point row ----
    #pragma unroll
    for (int off = 1; off < 4; off <<= 1) {
        #pragma unroll
        for (int hf = 0; hf < 2; hf++) {
            float ov = __shfl_xor_sync(0xffffffffu, best[hf], off);
            int   oi = __shfl_xor_sync(0xffffffffu, bi[hf],   off);
            if (ov < best[hf] || (ov == best[hf] && oi < bi[hf])) { best[hf] = ov; bi[hf] = oi; }
        }
    }
    if ((lane & 3) == 0) {
        int rA = p0 + (lane >> 2);
        if (base + rA < NPTS)     out_asg[base + rA]     = (float)bi[0];
        if (base + rA + 8 < NPTS) out_asg[base + rA + 8] = (float)bi[1];
    }
}

// ---------------- launch ----------------
extern "C" void kernel_launch(void* const* d_in, const int* in_sizes, int n_in,
                              void* d_out, int out_size) {
    const float* vecs = (const float*)d_in[0];
    const int*   asg  = (const int*)d_in[1];
    float* out      = (float*)d_out;
    float* out_cent = out;             // [KC*DIM]
    float* out_asg  = out + KC * DIM;  // [NPTS]

    zero_kernel<<<(KC * DIM + 255) / 256, 256>>>();
    segsum_kernel<<<(NPTS * 32) / 256, 256>>>(vecs, asg);
    finalize_kernel<<<KC, DIM>>>(out_cent);

    cudaFuncSetAttribute(argmin_mma_kernel,
                         cudaFuncAttributeMaxDynamicSharedMemorySize, SM_TOTAL);
    int ablocks = (NPTS + 127) / 128;
    argmin_mma_kernel<<<ablocks, 256, SM_TOTAL>>>(vecs, out_asg);
}

// round 5
// speedup vs baseline: 3.0414x; 1.7442x over previous
#include <cuda_runtime.h>
#include <cuda_fp16.h>
#include <cstdint>
#include <cstddef>

#define NPTS 500000
#define DIM  128
#define KC   1024

// ---------------- scratch ----------------
__device__ float g_sums[KC * DIM];
__device__ float g_counts[KC];
__device__ float g_c2[KC];
__device__ __half g_cent_hi[KC * DIM];   // fp16 splits of -2*centroid
__device__ __half g_cent_mi[KC * DIM];

// ---------------- helpers ----------------
__device__ __forceinline__ uint32_t smem_u32(const void* p) {
    uint32_t a;
    asm("{ .reg .u64 t; cvta.to.shared.u64 t, %1; cvt.u32.u64 %0, t; }" : "=r"(a) : "l"(p));
    return a;
}
__device__ __forceinline__ void ldsm_x4(uint32_t* r, uint32_t addr) {
    asm volatile("ldmatrix.sync.aligned.m8n8.x4.shared.b16 {%0,%1,%2,%3}, [%4];"
        : "=r"(r[0]), "=r"(r[1]), "=r"(r[2]), "=r"(r[3]) : "r"(addr));
}
__device__ __forceinline__ void mma_f16(float* d, const uint32_t* a, uint32_t b0, uint32_t b1) {
    asm volatile("mma.sync.aligned.m16n8k16.row.col.f32.f16.f16.f32 "
        "{%0,%1,%2,%3}, {%4,%5,%6,%7}, {%8,%9}, {%0,%1,%2,%3};"
        : "+f"(d[0]), "+f"(d[1]), "+f"(d[2]), "+f"(d[3])
        : "r"(a[0]), "r"(a[1]), "r"(a[2]), "r"(a[3]), "r"(b0), "r"(b1));
}
__device__ __forceinline__ void cp16(uint32_t dst, const void* src) {
    asm volatile("cp.async.cg.shared.global [%0], [%1], 16;" :: "r"(dst), "l"(src) : "memory");
}
#define CP_COMMIT() asm volatile("cp.async.commit_group;" ::: "memory")
#define CP_WAIT0()  asm volatile("cp.async.wait_group 0;" ::: "memory")
#define CP_WAIT1()  asm volatile("cp.async.wait_group 1;" ::: "memory")

// ---------------- kernel 1: zero scratch ----------------
__global__ void zero_kernel() {
    int i = blockIdx.x * blockDim.x + threadIdx.x;
    if (i < KC * DIM) g_sums[i] = 0.0f;
    if (i < KC)       g_counts[i] = 0.0f;
}

// ---------------- kernel 2: segment sum ----------------
__global__ void segsum_kernel(const float* __restrict__ vecs,
                              const int*   __restrict__ asg) {
    int gw   = (blockIdx.x * blockDim.x + threadIdx.x) >> 5;
    int lane = threadIdx.x & 31;
    if (gw >= NPTS) return;
    int k = asg[gw];
    float4 v = *((const float4*)(vecs + (size_t)gw * DIM) + lane);
    atomicAdd(((float4*)(g_sums + (size_t)k * DIM)) + lane, v);
    if (lane == 0) atomicAdd(&g_counts[k], 1.0f);
}

// ---------------- kernel 3: centroids, c2, -2c fp16 splits ----------------
__global__ void finalize_kernel(float* __restrict__ out_cent) {
    int k = blockIdx.x;
    int d = threadIdx.x;
    float c = g_sums[k * DIM + d] / g_counts[k];
    out_cent[k * DIM + d] = c;

    float m = -2.0f * c;
    __half h = __float2half_rn(m);
    __half mi = __float2half_rn(m - __half2float(h));
    g_cent_hi[k * DIM + d] = h;
    g_cent_mi[k * DIM + d] = mi;

    float s = c * c;
    #pragma unroll
    for (int o = 16; o > 0; o >>= 1) s += __shfl_down_sync(0xffffffffu, s, o);
    __shared__ float ws[4];
    if ((d & 31) == 0) ws[d >> 5] = s;
    __syncthreads();
    if (d == 0) g_c2[k] = (ws[0] + ws[1]) + (ws[2] + ws[3]);
}

// ---------------- kernel 4: mma.sync fp16-split GEMM + argmin ----------------
// 64 points/CTA x 1024 clusters. 4 warps; warp w owns points 16w..16w+15.
// A: 2 fp16 splits of points, swizzled smem [2][64][256B].
// B: 2 fp16 splits of -2c, 64-cluster chunks, cp.async double-buffered.
// 3 product passes (hh, hm, mh) accumulate into one fp32 D.
// 2 CTAs/SM (smem ~101KB) for cross-CTA latency hiding.
#define PTS_CTA 64
#define THR     128
#define CH_N    16
#define CHW     64
#define A_SPLIT 16384
#define A_OFF   0
#define B_OFF   32768
#define B_BUF   32768
#define B_SPLIT 16384
#define C2_OFF  98304
#define X2P_OFF 102400
#define X2_OFF  102912
#define SM_TOTAL 103168

__global__ __launch_bounds__(THR, 2)
void argmin_mma_kernel(const float* __restrict__ vecs, float* __restrict__ out_asg) {
    extern __shared__ __align__(1024) char sm[];
    const uint32_t su = smem_u32(sm);
    float* c2s = (float*)(sm + C2_OFF);
    float* x2p = (float*)(sm + X2P_OFF);
    float* x2s = (float*)(sm + X2_OFF);
    const int tid  = threadIdx.x;
    const int lane = tid & 31;
    const int w    = tid >> 5;
    const int base = blockIdx.x * PTS_CTA;

    // ---- issue chunk 0 B loads first (overlaps A convert) ----
    #pragma unroll
    for (int s = 0; s < 2; s++) {
        const __half* g = (s == 0) ? g_cent_hi : g_cent_mi;
        const char* gb = (const char*)g;   // chunk 0
        #pragma unroll
        for (int it = 0; it < 8; it++) {
            int idx = tid + it * THR;
            int row = idx >> 4, kg = idx & 15;
            uint32_t dst = su + B_OFF + (uint32_t)s * B_SPLIT + (uint32_t)row * 256u
                         + ((uint32_t)(kg ^ (row & 7)) << 4);
            cp16(dst, gb + (size_t)idx * 16);
        }
    }
    CP_COMMIT();

    for (int i = tid; i < KC; i += THR) c2s[i] = g_c2[i];

    // ---- A convert: fp32 -> 2x fp16 splits into swizzled smem; x2 partials ----
    {
        int p = tid >> 1, h = tid & 1;
        int n = base + p; if (n >= NPTS) n = NPTS - 1;
        const float4* src = (const float4*)(vecs + (size_t)n * DIM) + h * 16;
        float s2 = 0.0f;
        const uint32_t rowb = (uint32_t)p * 256u;
        const uint32_t psw  = (uint32_t)(p & 7);
        #pragma unroll
        for (int j = 0; j < 16; j++) {
            float4 v = src[j];
            int d0 = h * 64 + j * 4;
            #pragma unroll
            for (int q = 0; q < 2; q++) {
                float a0 = q ? v.z : v.x;
                float a1 = q ? v.w : v.y;
                int   d  = d0 + 2 * q;
                s2 = fmaf(a0, a0, s2); s2 = fmaf(a1, a1, s2);
                __half h0 = __float2half_rn(a0);
                __half m0 = __float2half_rn(a0 - __half2float(h0));
                __half h1 = __float2half_rn(a1);
                __half m1 = __float2half_rn(a1 - __half2float(h1));
                uint32_t off = rowb + ((((uint32_t)(d >> 3)) ^ psw) << 4) + (uint32_t)(d & 7) * 2u;
                __half2 ph(h0, h1), pm(m0, m1);
                *(uint32_t*)(sm + A_OFF + 0 * A_SPLIT + off) = *(uint32_t*)&ph;
                *(uint32_t*)(sm + A_OFF + 1 * A_SPLIT + off) = *(uint32_t*)&pm;
            }
        }
        x2p[tid] = s2;
    }
    __syncthreads();
    if (tid < PTS_CTA) x2s[tid] = x2p[2 * tid] + x2p[2 * tid + 1];

    const int p0 = w * 16;
    float best[2] = {3.402823466e38f, 3.402823466e38f};
    int   bi[2]   = {0, 0};

    const int arow = p0 + (lane & 15);
    const uint32_t abase = su + A_OFF + (uint32_t)arow * 256u;
    const uint32_t arsw  = (uint32_t)(arow & 7);
    const int akg  = lane >> 4;
    const int brow_local = ((lane >> 4) << 3) + (lane & 7);
    const int bkg_half   = (lane >> 3) & 1;

    for (int ch = 0; ch < CH_N; ch++) {
        const int buf = ch & 1;
        if (ch + 1 < CH_N) {
            #pragma unroll
            for (int s = 0; s < 2; s++) {
                const __half* g = (s == 0) ? g_cent_hi : g_cent_mi;
                const char* gb = (const char*)(g + (size_t)(ch + 1) * CHW * DIM);
                #pragma unroll
                for (int it = 0; it < 8; it++) {
                    int idx = tid + it * THR;
                    int row = idx >> 4, kg = idx & 15;
                    uint32_t dst = su + B_OFF + (uint32_t)(buf ^ 1) * B_BUF
                                 + (uint32_t)s * B_SPLIT + (uint32_t)row * 256u
                                 + ((uint32_t)(kg ^ (row & 7)) << 4);
                    cp16(dst, gb + (size_t)idx * 16);
                }
            }
            CP_COMMIT();
            CP_WAIT1();
        } else {
            CP_WAIT0();
        }
        __syncthreads();

        float D[8][4];
        #pragma unroll
        for (int i = 0; i < 8; i++)
            #pragma unroll
            for (int j = 0; j < 4; j++) D[i][j] = 0.0f;

        const uint32_t bbase = su + B_OFF + (uint32_t)buf * B_BUF;

        #pragma unroll
        for (int ks = 0; ks < 8; ks++) {
            uint32_t A_[2][4];
            {
                uint32_t ag = (uint32_t)(ks * 2 + akg);
                uint32_t asw = ((ag ^ arsw) << 4);
                ldsm_x4(A_[0], abase + 0 * A_SPLIT + asw);
                ldsm_x4(A_[1], abase + 1 * A_SPLIT + asw);
            }
            uint32_t B_[2][4][4];
            #pragma unroll
            for (int pp = 0; pp < 4; pp++) {
                int r  = pp * 16 + brow_local;
                int kg = ks * 2 + bkg_half;
                uint32_t bad = bbase + (uint32_t)r * 256u + ((uint32_t)(kg ^ (r & 7)) << 4);
                ldsm_x4(B_[0][pp], bad + 0 * B_SPLIT);
                ldsm_x4(B_[1][pp], bad + 1 * B_SPLIT);
            }
            // passes: (sa,sb) = hh, hm, mh
            const int SA[3] = {0, 0, 1};
            const int SB[3] = {0, 1, 0};
            #pragma unroll
            for (int p3 = 0; p3 < 3; p3++) {
                #pragma unroll
                for (int pp = 0; pp < 4; pp++) {
                    mma_f16(D[pp * 2 + 0], A_[SA[p3]], B_[SB[p3]][pp][0], B_[SB[p3]][pp][1]);
                    mma_f16(D[pp * 2 + 1], A_[SA[p3]], B_[SB[p3]][pp][2], B_[SB[p3]][pp][3]);
                }
            }
        }

        // ---- fold argmin (ascending cluster order within lane) ----
        float x2a = x2s[p0 + (lane >> 2)];
        float x2b = x2s[p0 + (lane >> 2) + 8];
        #pragma unroll
        for (int nt = 0; nt < 8; nt++) {
            int cb = ch * 64 + nt * 8 + 2 * (lane & 3);
            float c20 = c2s[cb], c21 = c2s[cb + 1];
            float v;
            v = (c20 + x2a) + D[nt][0]; if (v < best[0]) { best[0] = v; bi[0] = cb; }
            v = (c21 + x2a) + D[nt][1]; if (v < best[0]) { best[0] = v; bi[0] = cb + 1; }
            v = (c20 + x2b) + D[nt][2]; if (v < best[1]) { best[1] = v; bi[1] = cb; }
            v = (c21 + x2b) + D[nt][3]; if (v < best[1]) { best[1] = v; bi[1] = cb + 1; }
        }
        __syncthreads();
    }

    // ---- reduce across the 4 lanes sharing each point row ----
    #pragma unroll
    for (int off = 1; off < 4; off <<= 1) {
        #pragma unroll
        for (int hf = 0; hf < 2; hf++) {
            float ov = __shfl_xor_sync(0xffffffffu, best[hf], off);
            int   oi = __shfl_xor_sync(0xffffffffu, bi[hf],   off);
            if (ov < best[hf] || (ov == best[hf] && oi < bi[hf])) { best[hf] = ov; bi[hf] = oi; }
        }
    }
    if ((lane & 3) == 0) {
        int rA = p0 + (lane >> 2);
        if (base + rA < NPTS)     out_asg[base + rA]     = (float)bi[0];
        if (base + rA + 8 < NPTS) out_asg[base + rA + 8] = (float)bi[1];
    }
}

// ---------------- launch ----------------
extern "C" void kernel_launch(void* const* d_in, const int* in_sizes, int n_in,
                              void* d_out, int out_size) {
    const float* vecs = (const float*)d_in[0];
    const int*   asg  = (const int*)d_in[1];
    float* out      = (float*)d_out;
    float* out_cent = out;             // [KC*DIM]
    float* out_asg  = out + KC * DIM;  // [NPTS]

    zero_kernel<<<(KC * DIM + 255) / 256, 256>>>();
    segsum_kernel<<<(NPTS * 32) / 256, 256>>>(vecs, asg);
    finalize_kernel<<<KC, DIM>>>(out_cent);

    cudaFuncSetAttribute(argmin_mma_kernel,
                         cudaFuncAttributeMaxDynamicSharedMemorySize, SM_TOTAL);
    int ablocks = (NPTS + PTS_CTA - 1) / PTS_CTA;
    argmin_mma_kernel<<<ablocks, THR, SM_TOTAL>>>(vecs, out_asg);
}

// round 7
// speedup vs baseline: 3.1000x; 1.0192x over previous
#include <cuda_runtime.h>
#include <cuda_fp16.h>
#include <cstdint>
#include <cstddef>

#define NPTS 500000
#define DIM  128
#define KC   1024

// ---------------- scratch ----------------
__device__ float g_sums[KC * DIM];
__device__ float g_counts[KC];
__device__ float g_c2[KC];
__device__ __half g_cent_hi[KC * DIM];   // fp16 splits of -2*centroid
__device__ __half g_cent_mi[KC * DIM];

// ---------------- helpers ----------------
__device__ __forceinline__ uint32_t smem_u32(const void* p) {
    uint32_t a;
    asm("{ .reg .u64 t; cvta.to.shared.u64 t, %1; cvt.u32.u64 %0, t; }" : "=r"(a) : "l"(p));
    return a;
}
__device__ __forceinline__ void ldsm_x4(uint32_t* r, uint32_t addr) {
    asm volatile("ldmatrix.sync.aligned.m8n8.x4.shared.b16 {%0,%1,%2,%3}, [%4];"
        : "=r"(r[0]), "=r"(r[1]), "=r"(r[2]), "=r"(r[3]) : "r"(addr));
}
__device__ __forceinline__ void mma_f16(float* d, const uint32_t* a, uint32_t b0, uint32_t b1) {
    asm volatile("mma.sync.aligned.m16n8k16.row.col.f32.f16.f16.f32 "
        "{%0,%1,%2,%3}, {%4,%5,%6,%7}, {%8,%9}, {%0,%1,%2,%3};"
        : "+f"(d[0]), "+f"(d[1]), "+f"(d[2]), "+f"(d[3])
        : "r"(a[0]), "r"(a[1]), "r"(a[2]), "r"(a[3]), "r"(b0), "r"(b1));
}
__device__ __forceinline__ void cp16(uint32_t dst, const void* src) {
    asm volatile("cp.async.cg.shared.global [%0], [%1], 16;" :: "r"(dst), "l"(src) : "memory");
}
#define CP_COMMIT() asm volatile("cp.async.commit_group;" ::: "memory")
#define CP_WAIT0()  asm volatile("cp.async.wait_group 0;" ::: "memory")
#define CP_WAIT1()  asm volatile("cp.async.wait_group 1;" ::: "memory")

// ---------------- kernel 1: zero scratch ----------------
__global__ void zero_kernel() {
    int i = blockIdx.x * blockDim.x + threadIdx.x;
    if (i < KC * DIM) g_sums[i] = 0.0f;
    if (i < KC)       g_counts[i] = 0.0f;
}

// ---------------- kernel 2: segment sum ----------------
__global__ void segsum_kernel(const float* __restrict__ vecs,
                              const int*   __restrict__ asg) {
    int gw   = (blockIdx.x * blockDim.x + threadIdx.x) >> 5;
    int lane = threadIdx.x & 31;
    if (gw >= NPTS) return;
    int k = asg[gw];
    float4 v = *((const float4*)(vecs + (size_t)gw * DIM) + lane);
    atomicAdd(((float4*)(g_sums + (size_t)k * DIM)) + lane, v);
    if (lane == 0) atomicAdd(&g_counts[k], 1.0f);
}

// ---------------- kernel 3: centroids, c2, -2c fp16 splits ----------------
__global__ void finalize_kernel(float* __restrict__ out_cent) {
    int k = blockIdx.x;
    int d = threadIdx.x;
    float c = g_sums[k * DIM + d] / g_counts[k];
    out_cent[k * DIM + d] = c;

    float m = -2.0f * c;
    __half h = __float2half_rn(m);
    __half mi = __float2half_rn(m - __half2float(h));
    g_cent_hi[k * DIM + d] = h;
    g_cent_mi[k * DIM + d] = mi;

    float s = c * c;
    #pragma unroll
    for (int o = 16; o > 0; o >>= 1) s += __shfl_down_sync(0xffffffffu, s, o);
    __shared__ float ws[4];
    if ((d & 31) == 0) ws[d >> 5] = s;
    __syncthreads();
    if (d == 0) g_c2[k] = (ws[0] + ws[1]) + (ws[2] + ws[3]);
}

// ---------------- kernel 4: mma.sync fp16-split GEMM + argmin ----------------
// 64 points/CTA x 1024 clusters. 4 warps; warp w owns points 16w..16w+15.
// A: 2 fp16 splits of points, swizzled smem [2][64][256B].
// B: 2 fp16 splits of -2c, 32-cluster chunks, cp.async double-buffered.
// 3 product passes (hh, hm, mh) accumulate into one fp32 D.
// smem ~70KB -> 3 CTAs/SM (12 warps) for cross-CTA latency hiding.
#define PTS_CTA 64
#define THR     128
#define CH_N    32
#define CHW     32
#define A_SPLIT 16384
#define A_OFF   0
#define B_OFF   32768
#define B_BUF   16384
#define B_SPLIT 8192
#define C2_OFF  65536
#define X2P_OFF 69632
#define X2_OFF  70144
#define SM_TOTAL 70400

__global__ __launch_bounds__(THR, 3)
void argmin_mma_kernel(const float* __restrict__ vecs, float* __restrict__ out_asg) {
    extern __shared__ __align__(1024) char sm[];
    const uint32_t su = smem_u32(sm);
    float* c2s = (float*)(sm + C2_OFF);
    float* x2p = (float*)(sm + X2P_OFF);
    float* x2s = (float*)(sm + X2_OFF);
    const int tid  = threadIdx.x;
    const int lane = tid & 31;
    const int w    = tid >> 5;
    const int base = blockIdx.x * PTS_CTA;

    // ---- issue chunk 0 B loads first (overlaps A convert) ----
    #pragma unroll
    for (int s = 0; s < 2; s++) {
        const __half* g = (s == 0) ? g_cent_hi : g_cent_mi;
        const char* gb = (const char*)g;   // chunk 0
        #pragma unroll
        for (int it = 0; it < 4; it++) {
            int idx = tid + it * THR;          // 0..511
            int row = idx >> 4, kg = idx & 15;
            uint32_t dst = su + B_OFF + (uint32_t)s * B_SPLIT + (uint32_t)row * 256u
                         + ((uint32_t)(kg ^ (row & 7)) << 4);
            cp16(dst, gb + (size_t)idx * 16);
        }
    }
    CP_COMMIT();

    for (int i = tid; i < KC; i += THR) c2s[i] = g_c2[i];

    // ---- A convert: fp32 -> 2x fp16 splits into swizzled smem; x2 partials ----
    {
        int p = tid >> 1, h = tid & 1;
        int n = base + p; if (n >= NPTS) n = NPTS - 1;
        const float4* src = (const float4*)(vecs + (size_t)n * DIM) + h * 16;
        float s2 = 0.0f;
        const uint32_t rowb = (uint32_t)p * 256u;
        const uint32_t psw  = (uint32_t)(p & 7);
        #pragma unroll
        for (int j = 0; j < 16; j++) {
            float4 v = src[j];
            int d0 = h * 64 + j * 4;
            #pragma unroll
            for (int q = 0; q < 2; q++) {
                float a0 = q ? v.z : v.x;
                float a1 = q ? v.w : v.y;
                int   d  = d0 + 2 * q;
                s2 = fmaf(a0, a0, s2); s2 = fmaf(a1, a1, s2);
                __half h0 = __float2half_rn(a0);
                __half m0 = __float2half_rn(a0 - __half2float(h0));
                __half h1 = __float2half_rn(a1);
                __half m1 = __float2half_rn(a1 - __half2float(h1));
                uint32_t off = rowb + ((((uint32_t)(d >> 3)) ^ psw) << 4) + (uint32_t)(d & 7) * 2u;
                __half2 ph(h0, h1), pm(m0, m1);
                *(uint32_t*)(sm + A_OFF + 0 * A_SPLIT + off) = *(uint32_t*)&ph;
                *(uint32_t*)(sm + A_OFF + 1 * A_SPLIT + off) = *(uint32_t*)&pm;
            }
        }
        x2p[tid] = s2;
    }
    __syncthreads();
    if (tid < PTS_CTA) x2s[tid] = x2p[2 * tid] + x2p[2 * tid + 1];
    __syncthreads();

    const int p0 = w * 16;
    float best[2] = {3.402823466e38f, 3.402823466e38f};
    int   bi[2]   = {0, 0};

    const int arow = p0 + (lane & 15);
    const uint32_t abase = su + A_OFF + (uint32_t)arow * 256u;
    const uint32_t arsw  = (uint32_t)(arow & 7);
    const int akg  = lane >> 4;
    const int brow_local = ((lane >> 4) << 3) + (lane & 7);
    const int bkg_half   = (lane >> 3) & 1;

    const float x2a = x2s[p0 + (lane >> 2)];
    const float x2b = x2s[p0 + (lane >> 2) + 8];

    for (int ch = 0; ch < CH_N; ch++) {
        const int buf = ch & 1;
        if (ch + 1 < CH_N) {
            #pragma unroll
            for (int s = 0; s < 2; s++) {
                const __half* g = (s == 0) ? g_cent_hi : g_cent_mi;
                const char* gb = (const char*)(g + (size_t)(ch + 1) * CHW * DIM);
                #pragma unroll
                for (int it = 0; it < 4; it++) {
                    int idx = tid + it * THR;
                    int row = idx >> 4, kg = idx & 15;
                    uint32_t dst = su + B_OFF + (uint32_t)(buf ^ 1) * B_BUF
                                 + (uint32_t)s * B_SPLIT + (uint32_t)row * 256u
                                 + ((uint32_t)(kg ^ (row & 7)) << 4);
                    cp16(dst, gb + (size_t)idx * 16);
                }
            }
            CP_COMMIT();
            CP_WAIT1();
        } else {
            CP_WAIT0();
        }
        __syncthreads();

        float D[4][4];
        #pragma unroll
        for (int i = 0; i < 4; i++)
            #pragma unroll
            for (int j = 0; j < 4; j++) D[i][j] = 0.0f;

        const uint32_t bbase = su + B_OFF + (uint32_t)buf * B_BUF;

        #pragma unroll
        for (int ks = 0; ks < 8; ks++) {
            uint32_t A_[2][4];
            {
                uint32_t ag = (uint32_t)(ks * 2 + akg);
                uint32_t asw = ((ag ^ arsw) << 4);
                ldsm_x4(A_[0], abase + 0 * A_SPLIT + asw);
                ldsm_x4(A_[1], abase + 1 * A_SPLIT + asw);
            }
            uint32_t B_[2][2][4];
            #pragma unroll
            for (int pp = 0; pp < 2; pp++) {
                int r  = pp * 16 + brow_local;
                int kg = ks * 2 + bkg_half;
                uint32_t bad = bbase + (uint32_t)r * 256u + ((uint32_t)(kg ^ (r & 7)) << 4);
                ldsm_x4(B_[0][pp], bad + 0 * B_SPLIT);
                ldsm_x4(B_[1][pp], bad + 1 * B_SPLIT);
            }
            // passes: (sa,sb) = hh, hm, mh
            const int SA[3] = {0, 0, 1};
            const int SB[3] = {0, 1, 0};
            #pragma unroll
            for (int p3 = 0; p3 < 3; p3++) {
                #pragma unroll
                for (int pp = 0; pp < 2; pp++) {
                    mma_f16(D[pp * 2 + 0], A_[SA[p3]], B_[SB[p3]][pp][0], B_[SB[p3]][pp][1]);
                    mma_f16(D[pp * 2 + 1], A_[SA[p3]], B_[SB[p3]][pp][2], B_[SB[p3]][pp][3]);
                }
            }
        }

        // ---- fold argmin (ascending cluster order within lane) ----
        #pragma unroll
        for (int nt = 0; nt < 4; nt++) {
            int cb = ch * 32 + nt * 8 + 2 * (lane & 3);
            float c20 = c2s[cb], c21 = c2s[cb + 1];
            float v;
            v = (c20 + x2a) + D[nt][0]; if (v < best[0]) { best[0] = v; bi[0] = cb; }
            v = (c21 + x2a) + D[nt][1]; if (v < best[0]) { best[0] = v; bi[0] = cb + 1; }
            v = (c20 + x2b) + D[nt][2]; if (v < best[1]) { best[1] = v; bi[1] = cb; }
            v = (c21 + x2b) + D[nt][3]; if (v < best[1]) { best[1] = v; bi[1] = cb + 1; }
        }
        __syncthreads();
    }

    // ---- reduce across the 4 lanes sharing each point row ----
    #pragma unroll
    for (int off = 1; off < 4; off <<= 1) {
        #pragma unroll
        for (int hf = 0; hf < 2; hf++) {
            float ov = __shfl_xor_sync(0xffffffffu, best[hf], off);
            int   oi = __shfl_xor_sync(0xffffffffu, bi[hf],   off);
            if (ov < best[hf] || (ov == best[hf] && oi < bi[hf])) { best[hf] = ov; bi[hf] = oi; }
        }
    }
    if ((lane & 3) == 0) {
        int rA = p0 + (lane >> 2);
        if (base + rA < NPTS)     out_asg[base + rA]     = (float)bi[0];
        if (base + rA + 8 < NPTS) out_asg[base + rA + 8] = (float)bi[1];
    }
}

// ---------------- launch ----------------
extern "C" void kernel_launch(void* const* d_in, const int* in_sizes, int n_in,
                              void* d_out, int out_size) {
    const float* vecs = (const float*)d_in[0];
    const int*   asg  = (const int*)d_in[1];
    float* out      = (float*)d_out;
    float* out_cent = out;             // [KC*DIM]
    float* out_asg  = out + KC * DIM;  // [NPTS]

    zero_kernel<<<(KC * DIM + 255) / 256, 256>>>();
    segsum_kernel<<<(NPTS * 32) / 256, 256>>>(vecs, asg);
    finalize_kernel<<<KC, DIM>>>(out_cent);

    cudaFuncSetAttribute(argmin_mma_kernel,
                         cudaFuncAttributeMaxDynamicSharedMemorySize, SM_TOTAL);
    int ablocks = (NPTS + PTS_CTA - 1) / PTS_CTA;
    argmin_mma_kernel<<<ablocks, THR, SM_TOTAL>>>(vecs, out_asg);
}